// round 1
// baseline (speedup 1.0000x reference)
#include <cuda_runtime.h>
#include <math.h>

#define GN 40000
#define PN 5
#define UVE 65536          // 256*256
#define TM 128
#define NTILES ((GN + TM - 1) / TM)   // 313

// ---------------- scratch (device globals; no allocations) ----------------
__device__ int   g_counts[8];
__device__ int   g_offsets[8];
__device__ int   g_cursor[8];
__device__ int   g_order[GN];
__device__ float g_uvmap[32 * UVE];   // 8 MB
__device__ float g_bufA[64 * UVE];    // 16 MB
__device__ float g_bufB[64 * UVE];    // 16 MB
__device__ float g_mean[64];
__device__ float g_invstd[64];

// ---------------- part bucketing ----------------
__global__ void count_k(const int* __restrict__ part, int* counts) {
    int g = blockIdx.x * blockDim.x + threadIdx.x;
    if (g < GN) atomicAdd(&counts[part[g]], 1);
}
__global__ void scan_k(const int* __restrict__ counts, int* offsets, int* cursor) {
    if (threadIdx.x == 0) {
        int s = 0;
        for (int p = 0; p < PN; p++) { offsets[p] = s; cursor[p] = s; s += counts[p]; }
        offsets[PN] = s;
    }
}
__global__ void scatter_k(const int* __restrict__ part, int* cursor, int* __restrict__ order) {
    int g = blockIdx.x * blockDim.x + threadIdx.x;
    if (g < GN) { int pos = atomicAdd(&cursor[part[g]], 1); order[pos] = g; }
}

// ---------------- fused per-part MLP tile (all 8 layers in SMEM) ----------------
// Activations stored k-major in SMEM: A[k][r], r = gaussian row in tile.
// MODE 0: leaky-relu -> SMEM out. MODE 1: no act, masked cols -> SMEM out.
// MODE 2: no act, masked cols, scatter rows to uvmap.
template<int MODE>
__device__ __forceinline__ void layer_g(
    const float* __restrict__ A, int K,
    const float* __restrict__ W, int N,          // W row-major [K][N] in global
    const float* __restrict__ bias,
    float* Out, float* Bs, int tid,
    const int* s_uv, float* uvmap, int m)
{
    const int r0 = (tid >> 4) << 3;   // gaussian rows
    const int c0 = (tid & 15) << 3;   // neuron cols
    float acc[8][8];
#pragma unroll
    for (int i = 0; i < 8; i++)
#pragma unroll
        for (int j = 0; j < 8; j++) acc[i][j] = 0.f;

    for (int kb = 0; kb < K; kb += 16) {
        // stage 16x128 weight chunk (zero-padded)
#pragma unroll
        for (int t2 = 0; t2 < 8; t2++) {
            int e = tid + t2 * 256;
            int kk = e >> 7, j = e & 127;
            int k = kb + kk;
            Bs[e] = (k < K && j < N) ? W[k * N + j] : 0.f;
        }
        __syncthreads();
#pragma unroll
        for (int kk = 0; kk < 16; kk++) {
            const float* Ak = A + (kb + kk) * 128;
            float4 a0 = *(const float4*)(Ak + r0);
            float4 a1 = *(const float4*)(Ak + r0 + 4);
            const float* Bk = Bs + kk * 128;
            float4 b0 = *(const float4*)(Bk + c0);
            float4 b1 = *(const float4*)(Bk + c0 + 4);
            float av[8] = {a0.x, a0.y, a0.z, a0.w, a1.x, a1.y, a1.z, a1.w};
            float bv[8] = {b0.x, b0.y, b0.z, b0.w, b1.x, b1.y, b1.z, b1.w};
#pragma unroll
            for (int i = 0; i < 8; i++)
#pragma unroll
                for (int j = 0; j < 8; j++) acc[i][j] += av[i] * bv[j];
        }
        __syncthreads();
    }

    float bj[8];
#pragma unroll
    for (int j = 0; j < 8; j++) bj[j] = (c0 + j < N) ? bias[c0 + j] : 0.f;

    if (MODE == 0) {
#pragma unroll
        for (int j = 0; j < 8; j++) {
            float4 v0, v1;
            float t;
            t = acc[0][j] + bj[j]; v0.x = t > 0.f ? t : 0.01f * t;
            t = acc[1][j] + bj[j]; v0.y = t > 0.f ? t : 0.01f * t;
            t = acc[2][j] + bj[j]; v0.z = t > 0.f ? t : 0.01f * t;
            t = acc[3][j] + bj[j]; v0.w = t > 0.f ? t : 0.01f * t;
            t = acc[4][j] + bj[j]; v1.x = t > 0.f ? t : 0.01f * t;
            t = acc[5][j] + bj[j]; v1.y = t > 0.f ? t : 0.01f * t;
            t = acc[6][j] + bj[j]; v1.z = t > 0.f ? t : 0.01f * t;
            t = acc[7][j] + bj[j]; v1.w = t > 0.f ? t : 0.01f * t;
            *(float4*)(Out + (c0 + j) * 128 + r0) = v0;
            *(float4*)(Out + (c0 + j) * 128 + r0 + 4) = v1;
        }
    } else if (MODE == 1) {
#pragma unroll
        for (int j = 0; j < 8; j++) {
            if (c0 + j < N) {
#pragma unroll
                for (int i = 0; i < 8; i++)
                    Out[(c0 + j) * 128 + r0 + i] = acc[i][j] + bj[j];
            }
        }
    } else {
#pragma unroll
        for (int j = 0; j < 8; j++) {
            if (c0 + j < N) {
#pragma unroll
                for (int i = 0; i < 8; i++) {
                    if (r0 + i < m)
                        uvmap[(c0 + j) * UVE + s_uv[r0 + i]] = acc[i][j] + bj[j];
                }
            }
        }
    }
    __syncthreads();
}

__global__ __launch_bounds__(256, 1)
void mlp_k(const float* __restrict__ latent_z, const float* __restrict__ latent_f,
           const float* __restrict__ cano_xyz,
           const float* __restrict__ m1_w_in, const float* __restrict__ m1_b_in,
           const float* __restrict__ m1_w_hid, const float* __restrict__ m1_b_hid,
           const float* __restrict__ m1_w_out, const float* __restrict__ m1_b_out,
           const float* __restrict__ m2_w_in, const float* __restrict__ m2_b_in,
           const float* __restrict__ m2_w_hid, const float* __restrict__ m2_b_hid,
           const float* __restrict__ m2_w_out, const float* __restrict__ m2_b_out,
           const int* __restrict__ uv_idx,
           const int* __restrict__ order, const int* __restrict__ offsets,
           float* __restrict__ uvmap)
{
    extern __shared__ float sm[];
    float* Xs = sm;                       // [112][128] (rows 0..95 x1, 96..98 xyz, 99..109 attrs, 110..111 zero)
    float* Hp = Xs + 112 * 128;           // [128][128]
    float* Hq = Hp + 128 * 128;           // [128][128]
    float* Bs = Hq + 128 * 128;           // [16][128]
    int*   s_idx = (int*)(Bs + 16 * 128); // [128]
    int*   s_uv  = s_idx + 128;           // [128]

    int p = blockIdx.x / NTILES;
    int t = blockIdx.x % NTILES;
    int beg = offsets[p], end = offsets[p + 1];
    int start = beg + t * TM;
    if (start >= end) return;
    int m = min(TM, end - start);
    int tid = threadIdx.x;

    if (tid < TM) {
        int rr = tid < m ? tid : (m - 1);
        int gid = order[start + rr];
        s_idx[tid] = gid;
        s_uv[tid] = uv_idx[gid];
    }
    __syncthreads();

    // gather X (k-major). latent_f broadcast within block (single part).
    for (int e = tid; e < 112 * TM; e += 256) {
        int d = e >> 7, r = e & 127;
        float v = 0.f;
        if (d < 64)       v = latent_f[p * 64 + d];
        else if (d < 96)  v = latent_z[s_idx[r] * 32 + (d - 64)];
        else if (d < 99)  v = cano_xyz[s_idx[r] * 3 + (d - 96)];
        Xs[d * 128 + r] = v;
    }
    __syncthreads();

    // ---- MLP1 ----
    layer_g<0>(Xs, 96,  m1_w_in  + p * 96 * 128, 128, m1_b_in  + p * 128, Hp, Bs, tid, 0, 0, m);
    layer_g<0>(Hp, 128, m1_w_hid + (p * 2 + 0) * 16384, 128, m1_b_hid + (p * 2 + 0) * 128, Hq, Bs, tid, 0, 0, m);
    layer_g<0>(Hq, 128, m1_w_hid + (p * 2 + 1) * 16384, 128, m1_b_hid + (p * 2 + 1) * 128, Hp, Bs, tid, 0, 0, m);
    layer_g<1>(Hp, 128, m1_w_out + p * 128 * 11, 11, m1_b_out + p * 11, Xs + 99 * 128, Bs, tid, 0, 0, m);
    // ---- MLP2 ----
    layer_g<0>(Xs, 110, m2_w_in  + p * 110 * 128, 128, m2_b_in  + p * 128, Hp, Bs, tid, 0, 0, m);
    layer_g<0>(Hp, 128, m2_w_hid + (p * 2 + 0) * 16384, 128, m2_b_hid + (p * 2 + 0) * 128, Hq, Bs, tid, 0, 0, m);
    layer_g<0>(Hq, 128, m2_w_hid + (p * 2 + 1) * 16384, 128, m2_b_hid + (p * 2 + 1) * 128, Hp, Bs, tid, 0, 0, m);
    layer_g<2>(Hp, 128, m2_w_out + p * 128 * 32, 32, m2_b_out + p * 32, 0, Bs, tid, s_uv, uvmap, m);
}

// ---------------- CNN ----------------
// 16x16 output pixels x 64 couts per block. 256 threads: 64 pixel-groups (2x2 px) x 4 cout-groups (16 co).
template<int CIN, bool RELU, bool NORM>
__global__ __launch_bounds__(256)
void conv64_k(const float* __restrict__ in, const float* __restrict__ w,
              const float* __restrict__ bias,
              const float* __restrict__ mean, const float* __restrict__ invstd,
              float* __restrict__ out)
{
    __shared__ float tile[18 * 18];
    __shared__ float ws[64 * 9];
    int bx = blockIdx.x;
    int x0 = (bx & 15) << 4, y0 = (bx >> 4) << 4;
    int tid = threadIdx.x;
    int pg = tid & 63, cg = tid >> 6;
    int lx = (pg & 7) * 2, ly = (pg >> 3) * 2;

    float acc[16][4];
#pragma unroll
    for (int c = 0; c < 16; c++)
#pragma unroll
        for (int q = 0; q < 4; q++) acc[c][q] = 0.f;

    for (int cin = 0; cin < CIN; cin++) {
        float mn = 0.f, is = 1.f;
        if (NORM) { mn = mean[cin]; is = invstd[cin]; }
        for (int e = tid; e < 324; e += 256) {
            int iy = y0 + (e / 18) - 1, ix = x0 + (e % 18) - 1;
            float v = 0.f;
            if (iy >= 0 && iy < 256 && ix >= 0 && ix < 256) {
                v = in[cin * UVE + iy * 256 + ix];
                if (NORM) v = (v - mn) * is;
                if (RELU) v = fmaxf(v, 0.f);
            }
            tile[e] = v;
        }
        for (int e = tid; e < 64 * 9; e += 256)
            ws[e] = w[((e / 9) * CIN + cin) * 9 + (e % 9)];
        __syncthreads();

        float pr[4][4];
#pragma unroll
        for (int dy = 0; dy < 4; dy++)
#pragma unroll
            for (int dx = 0; dx < 4; dx++)
                pr[dy][dx] = tile[(ly + dy) * 18 + lx + dx];

#pragma unroll
        for (int co = 0; co < 16; co++) {
            const float* wp = ws + (cg * 16 + co) * 9;
#pragma unroll
            for (int ky = 0; ky < 3; ky++)
#pragma unroll
                for (int kx = 0; kx < 3; kx++) {
                    float wv = wp[ky * 3 + kx];
                    acc[co][0] += wv * pr[ky][kx];
                    acc[co][1] += wv * pr[ky][kx + 1];
                    acc[co][2] += wv * pr[ky + 1][kx];
                    acc[co][3] += wv * pr[ky + 1][kx + 1];
                }
        }
        __syncthreads();
    }

#pragma unroll
    for (int co = 0; co < 16; co++) {
        int c = cg * 16 + co;
        float b = bias[c];
        float* o = out + c * UVE + (y0 + ly) * 256 + (x0 + lx);
        o[0]   = acc[co][0] + b;
        o[1]   = acc[co][1] + b;
        o[256] = acc[co][2] + b;
        o[257] = acc[co][3] + b;
    }
}

__global__ void stats_k(const float* __restrict__ buf, float* mean, float* invstd) {
    __shared__ float s1[256], s2[256];
    int c = blockIdx.x, tid = threadIdx.x;
    float a = 0.f, b = 0.f;
    for (int i = tid; i < UVE; i += 256) {
        float v = buf[c * UVE + i];
        a += v; b += v * v;
    }
    s1[tid] = a; s2[tid] = b;
    __syncthreads();
    for (int s = 128; s > 0; s >>= 1) {
        if (tid < s) { s1[tid] += s1[tid + s]; s2[tid] += s2[tid + s]; }
        __syncthreads();
    }
    if (tid == 0) {
        float mu = s1[0] * (1.f / UVE);
        float var = s2[0] * (1.f / UVE) - mu * mu;
        mean[c] = mu;
        invstd[c] = rsqrtf(var + 1e-5f);
    }
}

// conv_out: 64 -> 3, norm input (no relu), sigmoid epilogue. One pixel per thread.
__global__ __launch_bounds__(256)
void conv_out_k(const float* __restrict__ in, const float* __restrict__ w,
                const float* __restrict__ bias,
                const float* __restrict__ mean, const float* __restrict__ invstd,
                float* __restrict__ out)
{
    __shared__ float ws[3 * 64 * 9];
    __shared__ float tile[18 * 18];
    int bx = blockIdx.x;
    int x0 = (bx & 15) << 4, y0 = (bx >> 4) << 4;
    int tid = threadIdx.x;
    int px = tid & 15, py = tid >> 4;

    for (int e = tid; e < 3 * 64 * 9; e += 256) ws[e] = w[e];

    float a0 = 0.f, a1 = 0.f, a2 = 0.f;
    for (int cin = 0; cin < 64; cin++) {
        float mn = mean[cin], is = invstd[cin];
        for (int e = tid; e < 324; e += 256) {
            int iy = y0 + (e / 18) - 1, ix = x0 + (e % 18) - 1;
            float v = 0.f;
            if (iy >= 0 && iy < 256 && ix >= 0 && ix < 256)
                v = (in[cin * UVE + iy * 256 + ix] - mn) * is;
            tile[e] = v;
        }
        __syncthreads();
        float pr[9];
#pragma unroll
        for (int ky = 0; ky < 3; ky++)
#pragma unroll
            for (int kx = 0; kx < 3; kx++)
                pr[ky * 3 + kx] = tile[(py + ky) * 18 + px + kx];
#pragma unroll
        for (int k = 0; k < 9; k++) {
            a0 += pr[k] * ws[(0 * 64 + cin) * 9 + k];
            a1 += pr[k] * ws[(1 * 64 + cin) * 9 + k];
            a2 += pr[k] * ws[(2 * 64 + cin) * 9 + k];
        }
        __syncthreads();
    }
    int o = (y0 + py) * 256 + (x0 + px);
    a0 += bias[0]; a1 += bias[1]; a2 += bias[2];
    out[0 * UVE + o] = 1.f / (1.f + expf(-a0));
    out[1 * UVE + o] = 1.f / (1.f + expf(-a1));
    out[2 * UVE + o] = 1.f / (1.f + expf(-a2));
}

// ---------------- launch ----------------
extern "C" void kernel_launch(void* const* d_in, const int* in_sizes, int n_in,
                              void* d_out, int out_size)
{
    const float* latent_z  = (const float*)d_in[0];
    const float* latent_f  = (const float*)d_in[1];
    const float* cano_xyz  = (const float*)d_in[2];
    const float* m1_w_in   = (const float*)d_in[3];
    const float* m1_b_in   = (const float*)d_in[4];
    const float* m1_w_hid  = (const float*)d_in[5];
    const float* m1_b_hid  = (const float*)d_in[6];
    const float* m1_w_out  = (const float*)d_in[7];
    const float* m1_b_out  = (const float*)d_in[8];
    const float* m2_w_in   = (const float*)d_in[9];
    const float* m2_b_in   = (const float*)d_in[10];
    const float* m2_w_hid  = (const float*)d_in[11];
    const float* m2_b_hid  = (const float*)d_in[12];
    const float* m2_w_out  = (const float*)d_in[13];
    const float* m2_b_out  = (const float*)d_in[14];
    const float* conv_in_w = (const float*)d_in[15];
    const float* conv_in_b = (const float*)d_in[16];
    const float* conv_hid_w= (const float*)d_in[17];
    const float* conv_hid_b= (const float*)d_in[18];
    const float* conv_out_w= (const float*)d_in[19];
    const float* conv_out_b= (const float*)d_in[20];
    const int*   gs_part   = (const int*)d_in[21];
    const int*   uv_idx    = (const int*)d_in[22];
    float* outp = (float*)d_out;

    void *p_counts, *p_offsets, *p_cursor, *p_order, *p_uvmap, *p_bufA, *p_bufB, *p_mean, *p_invstd;
    cudaGetSymbolAddress(&p_counts, g_counts);
    cudaGetSymbolAddress(&p_offsets, g_offsets);
    cudaGetSymbolAddress(&p_cursor, g_cursor);
    cudaGetSymbolAddress(&p_order, g_order);
    cudaGetSymbolAddress(&p_uvmap, g_uvmap);
    cudaGetSymbolAddress(&p_bufA, g_bufA);
    cudaGetSymbolAddress(&p_bufB, g_bufB);
    cudaGetSymbolAddress(&p_mean, g_mean);
    cudaGetSymbolAddress(&p_invstd, g_invstd);

    cudaMemsetAsync(p_counts, 0, 8 * sizeof(int), 0);
    cudaMemsetAsync(p_uvmap, 0, 32 * UVE * sizeof(float), 0);

    int gb = (GN + 255) / 256;
    count_k<<<gb, 256>>>(gs_part, (int*)p_counts);
    scan_k<<<1, 32>>>((const int*)p_counts, (int*)p_offsets, (int*)p_cursor);
    scatter_k<<<gb, 256>>>(gs_part, (int*)p_cursor, (int*)p_order);

    static bool attr_set = false;
    if (!attr_set) {
        cudaFuncSetAttribute(mlp_k, cudaFuncAttributeMaxDynamicSharedMemorySize, 197632);
        attr_set = true;
    }
    mlp_k<<<PN * NTILES, 256, 197632>>>(
        latent_z, latent_f, cano_xyz,
        m1_w_in, m1_b_in, m1_w_hid, m1_b_hid, m1_w_out, m1_b_out,
        m2_w_in, m2_b_in, m2_w_hid, m2_b_hid, m2_w_out, m2_b_out,
        uv_idx, (const int*)p_order, (const int*)p_offsets, (float*)p_uvmap);

    float* bufA = (float*)p_bufA;
    float* bufB = (float*)p_bufB;
    float* mean = (float*)p_mean;
    float* invstd = (float*)p_invstd;

    // conv_in: uvmap(32) -> bufA(64), no relu, no norm
    conv64_k<32, false, false><<<256, 256>>>((const float*)p_uvmap, conv_in_w, conv_in_b, 0, 0, bufA);
    // hidden 0: relu(bufA) -> conv -> bufB; stats(bufB)
    conv64_k<64, true, false><<<256, 256>>>(bufA, conv_hid_w + 0 * 36864, conv_hid_b + 0, 0, 0, bufB);
    stats_k<<<64, 256>>>(bufB, mean, invstd);
    // hidden 1: relu(norm(bufB)) -> conv -> bufA; stats(bufA)
    conv64_k<64, true, true><<<256, 256>>>(bufB, conv_hid_w + 1 * 36864, conv_hid_b + 64, mean, invstd, bufA);
    stats_k<<<64, 256>>>(bufA, mean, invstd);
    // hidden 2: relu(norm(bufA)) -> conv -> bufB; stats(bufB)
    conv64_k<64, true, true><<<256, 256>>>(bufA, conv_hid_w + 2 * 36864, conv_hid_b + 128, mean, invstd, bufB);
    stats_k<<<64, 256>>>(bufB, mean, invstd);
    // conv_out: norm(bufB) -> conv(3) -> sigmoid -> out
    conv_out_k<<<256, 256>>>(bufB, conv_out_w, conv_out_b, mean, invstd, outp);
}

// round 2
// speedup vs baseline: 1.0121x; 1.0121x over previous
#include <cuda_runtime.h>
#include <math.h>

#define GN 40000
#define PN 5
#define UVE 65536          // 256*256
#define TM 128
#define NTILES ((GN + TM - 1) / TM)   // 313

// ---------------- scratch (device globals; no allocations) ----------------
__device__ int   g_counts[8];
__device__ int   g_offsets[8];
__device__ int   g_cursor[8];
__device__ int   g_order[GN];
__device__ float g_uvmap[32 * UVE];   // 8 MB
__device__ float g_bufA[64 * UVE];    // 16 MB
__device__ float g_bufB[64 * UVE];    // 16 MB
__device__ float g_mean[64];
__device__ float g_invstd[64];

// ---------------- part bucketing ----------------
__global__ void count_k(const int* __restrict__ part, int* counts) {
    int g = blockIdx.x * blockDim.x + threadIdx.x;
    if (g < GN) atomicAdd(&counts[part[g]], 1);
}
__global__ void scan_k(const int* __restrict__ counts, int* offsets, int* cursor) {
    if (threadIdx.x == 0) {
        int s = 0;
        for (int p = 0; p < PN; p++) { offsets[p] = s; cursor[p] = s; s += counts[p]; }
        offsets[PN] = s;
    }
}
__global__ void scatter_k(const int* __restrict__ part, int* cursor, int* __restrict__ order) {
    int g = blockIdx.x * blockDim.x + threadIdx.x;
    if (g < GN) { int pos = atomicAdd(&cursor[part[g]], 1); order[pos] = g; }
}

// ---------------- fused per-part MLP tile (all 8 layers in SMEM) ----------------
// Activations stored k-major in SMEM: A[k][r], r = gaussian row in tile.
// MODE 0: leaky-relu -> SMEM out. MODE 1: no act, masked cols -> SMEM out.
// MODE 2: no act, masked cols, scatter rows to uvmap.
template<int MODE>
__device__ __forceinline__ void layer_g(
    const float* __restrict__ A, int K,
    const float* __restrict__ W, int N,          // W row-major [K][N] in global
    const float* __restrict__ bias,
    float* Out, float* Bs, int tid,
    const int* s_uv, float* uvmap, int m)
{
    const int r0 = (tid >> 4) << 3;   // gaussian rows
    const int c0 = (tid & 15) << 3;   // neuron cols
    float acc[8][8];
#pragma unroll
    for (int i = 0; i < 8; i++)
#pragma unroll
        for (int j = 0; j < 8; j++) acc[i][j] = 0.f;

    for (int kb = 0; kb < K; kb += 16) {
        // stage 16x128 weight chunk (zero-padded)
#pragma unroll
        for (int t2 = 0; t2 < 8; t2++) {
            int e = tid + t2 * 256;
            int kk = e >> 7, j = e & 127;
            int k = kb + kk;
            Bs[e] = (k < K && j < N) ? W[k * N + j] : 0.f;
        }
        __syncthreads();
#pragma unroll
        for (int kk = 0; kk < 16; kk++) {
            const float* Ak = A + (kb + kk) * 128;
            float4 a0 = *(const float4*)(Ak + r0);
            float4 a1 = *(const float4*)(Ak + r0 + 4);
            const float* Bk = Bs + kk * 128;
            float4 b0 = *(const float4*)(Bk + c0);
            float4 b1 = *(const float4*)(Bk + c0 + 4);
            float av[8] = {a0.x, a0.y, a0.z, a0.w, a1.x, a1.y, a1.z, a1.w};
            float bv[8] = {b0.x, b0.y, b0.z, b0.w, b1.x, b1.y, b1.z, b1.w};
#pragma unroll
            for (int i = 0; i < 8; i++)
#pragma unroll
                for (int j = 0; j < 8; j++) acc[i][j] += av[i] * bv[j];
        }
        __syncthreads();
    }

    float bj[8];
#pragma unroll
    for (int j = 0; j < 8; j++) bj[j] = (c0 + j < N) ? bias[c0 + j] : 0.f;

    if (MODE == 0) {
#pragma unroll
        for (int j = 0; j < 8; j++) {
            float4 v0, v1;
            float t;
            t = acc[0][j] + bj[j]; v0.x = t > 0.f ? t : 0.01f * t;
            t = acc[1][j] + bj[j]; v0.y = t > 0.f ? t : 0.01f * t;
            t = acc[2][j] + bj[j]; v0.z = t > 0.f ? t : 0.01f * t;
            t = acc[3][j] + bj[j]; v0.w = t > 0.f ? t : 0.01f * t;
            t = acc[4][j] + bj[j]; v1.x = t > 0.f ? t : 0.01f * t;
            t = acc[5][j] + bj[j]; v1.y = t > 0.f ? t : 0.01f * t;
            t = acc[6][j] + bj[j]; v1.z = t > 0.f ? t : 0.01f * t;
            t = acc[7][j] + bj[j]; v1.w = t > 0.f ? t : 0.01f * t;
            *(float4*)(Out + (c0 + j) * 128 + r0) = v0;
            *(float4*)(Out + (c0 + j) * 128 + r0 + 4) = v1;
        }
    } else if (MODE == 1) {
#pragma unroll
        for (int j = 0; j < 8; j++) {
            if (c0 + j < N) {
#pragma unroll
                for (int i = 0; i < 8; i++)
                    Out[(c0 + j) * 128 + r0 + i] = acc[i][j] + bj[j];
            }
        }
    } else {
#pragma unroll
        for (int j = 0; j < 8; j++) {
            if (c0 + j < N) {
#pragma unroll
                for (int i = 0; i < 8; i++) {
                    if (r0 + i < m)
                        uvmap[(c0 + j) * UVE + s_uv[r0 + i]] = acc[i][j] + bj[j];
                }
            }
        }
    }
    __syncthreads();
}

__global__ __launch_bounds__(256, 1)
void mlp_k(const float* __restrict__ latent_z, const float* __restrict__ latent_f,
           const float* __restrict__ cano_xyz,
           const float* __restrict__ m1_w_in, const float* __restrict__ m1_b_in,
           const float* __restrict__ m1_w_hid, const float* __restrict__ m1_b_hid,
           const float* __restrict__ m1_w_out, const float* __restrict__ m1_b_out,
           const float* __restrict__ m2_w_in, const float* __restrict__ m2_b_in,
           const float* __restrict__ m2_w_hid, const float* __restrict__ m2_b_hid,
           const float* __restrict__ m2_w_out, const float* __restrict__ m2_b_out,
           const int* __restrict__ uv_idx,
           const int* __restrict__ order, const int* __restrict__ offsets,
           float* __restrict__ uvmap)
{
    extern __shared__ float sm[];
    float* Xs = sm;                       // [112][128] (rows 0..95 x1, 96..98 xyz, 99..109 attrs, 110..111 zero)
    float* Hp = Xs + 112 * 128;           // [128][128]
    float* Hq = Hp + 128 * 128;           // [128][128]
    float* Bs = Hq + 128 * 128;           // [16][128]
    int*   s_idx = (int*)(Bs + 16 * 128); // [128]
    int*   s_uv  = s_idx + 128;           // [128]

    int p = blockIdx.x / NTILES;
    int t = blockIdx.x % NTILES;
    int beg = offsets[p], end = offsets[p + 1];
    int start = beg + t * TM;
    if (start >= end) return;
    int m = min(TM, end - start);
    int tid = threadIdx.x;

    if (tid < TM) {
        int rr = tid < m ? tid : (m - 1);
        int gid = order[start + rr];
        s_idx[tid] = gid;
        s_uv[tid] = uv_idx[gid];
    }
    __syncthreads();

    // gather X (k-major). latent_f broadcast within block (single part).
    for (int e = tid; e < 112 * TM; e += 256) {
        int d = e >> 7, r = e & 127;
        float v = 0.f;
        if (d < 64)       v = latent_f[p * 64 + d];
        else if (d < 96)  v = latent_z[s_idx[r] * 32 + (d - 64)];
        else if (d < 99)  v = cano_xyz[s_idx[r] * 3 + (d - 96)];
        Xs[d * 128 + r] = v;
    }
    __syncthreads();

    // ---- MLP1 ----
    layer_g<0>(Xs, 96,  m1_w_in  + p * 96 * 128, 128, m1_b_in  + p * 128, Hp, Bs, tid, 0, 0, m);
    layer_g<0>(Hp, 128, m1_w_hid + (p * 2 + 0) * 16384, 128, m1_b_hid + (p * 2 + 0) * 128, Hq, Bs, tid, 0, 0, m);
    layer_g<0>(Hq, 128, m1_w_hid + (p * 2 + 1) * 16384, 128, m1_b_hid + (p * 2 + 1) * 128, Hp, Bs, tid, 0, 0, m);
    layer_g<1>(Hp, 128, m1_w_out + p * 128 * 11, 11, m1_b_out + p * 11, Xs + 99 * 128, Bs, tid, 0, 0, m);
    // ---- MLP2 ----
    layer_g<0>(Xs, 110, m2_w_in  + p * 110 * 128, 128, m2_b_in  + p * 128, Hp, Bs, tid, 0, 0, m);
    layer_g<0>(Hp, 128, m2_w_hid + (p * 2 + 0) * 16384, 128, m2_b_hid + (p * 2 + 0) * 128, Hq, Bs, tid, 0, 0, m);
    layer_g<0>(Hq, 128, m2_w_hid + (p * 2 + 1) * 16384, 128, m2_b_hid + (p * 2 + 1) * 128, Hp, Bs, tid, 0, 0, m);
    layer_g<2>(Hp, 128, m2_w_out + p * 128 * 32, 32, m2_b_out + p * 32, 0, Bs, tid, s_uv, uvmap, m);
}

// ---------------- CNN ----------------
// 16x16 output pixels x 64 couts per block. 256 threads: 64 pixel-groups (2x2 px) x 4 cout-groups (16 co).
template<int CIN, bool RELU, bool NORM>
__global__ __launch_bounds__(256)
void conv64_k(const float* __restrict__ in, const float* __restrict__ w,
              const float* __restrict__ bias,
              const float* __restrict__ mean, const float* __restrict__ invstd,
              float* __restrict__ out)
{
    __shared__ float tile[18 * 18];
    __shared__ float ws[64 * 9];
    int bx = blockIdx.x;
    int x0 = (bx & 15) << 4, y0 = (bx >> 4) << 4;
    int tid = threadIdx.x;
    int pg = tid & 63, cg = tid >> 6;
    int lx = (pg & 7) * 2, ly = (pg >> 3) * 2;

    float acc[16][4];
#pragma unroll
    for (int c = 0; c < 16; c++)
#pragma unroll
        for (int q = 0; q < 4; q++) acc[c][q] = 0.f;

    for (int cin = 0; cin < CIN; cin++) {
        float mn = 0.f, is = 1.f;
        if (NORM) { mn = mean[cin]; is = invstd[cin]; }
        for (int e = tid; e < 324; e += 256) {
            int iy = y0 + (e / 18) - 1, ix = x0 + (e % 18) - 1;
            float v = 0.f;
            if (iy >= 0 && iy < 256 && ix >= 0 && ix < 256) {
                v = in[cin * UVE + iy * 256 + ix];
                if (NORM) v = (v - mn) * is;
                if (RELU) v = fmaxf(v, 0.f);
            }
            tile[e] = v;
        }
        for (int e = tid; e < 64 * 9; e += 256)
            ws[e] = w[((e / 9) * CIN + cin) * 9 + (e % 9)];
        __syncthreads();

        float pr[4][4];
#pragma unroll
        for (int dy = 0; dy < 4; dy++)
#pragma unroll
            for (int dx = 0; dx < 4; dx++)
                pr[dy][dx] = tile[(ly + dy) * 18 + lx + dx];

#pragma unroll
        for (int co = 0; co < 16; co++) {
            const float* wp = ws + (cg * 16 + co) * 9;
#pragma unroll
            for (int ky = 0; ky < 3; ky++)
#pragma unroll
                for (int kx = 0; kx < 3; kx++) {
                    float wv = wp[ky * 3 + kx];
                    acc[co][0] += wv * pr[ky][kx];
                    acc[co][1] += wv * pr[ky][kx + 1];
                    acc[co][2] += wv * pr[ky + 1][kx];
                    acc[co][3] += wv * pr[ky + 1][kx + 1];
                }
        }
        __syncthreads();
    }

#pragma unroll
    for (int co = 0; co < 16; co++) {
        int c = cg * 16 + co;
        float b = bias[c];
        float* o = out + c * UVE + (y0 + ly) * 256 + (x0 + lx);
        o[0]   = acc[co][0] + b;
        o[1]   = acc[co][1] + b;
        o[256] = acc[co][2] + b;
        o[257] = acc[co][3] + b;
    }
}

__global__ void stats_k(const float* __restrict__ buf, float* mean, float* invstd) {
    __shared__ float s1[256], s2[256];
    int c = blockIdx.x, tid = threadIdx.x;
    float a = 0.f, b = 0.f;
    for (int i = tid; i < UVE; i += 256) {
        float v = buf[c * UVE + i];
        a += v; b += v * v;
    }
    s1[tid] = a; s2[tid] = b;
    __syncthreads();
    for (int s = 128; s > 0; s >>= 1) {
        if (tid < s) { s1[tid] += s1[tid + s]; s2[tid] += s2[tid + s]; }
        __syncthreads();
    }
    if (tid == 0) {
        float mu = s1[0] * (1.f / UVE);
        float var = s2[0] * (1.f / UVE) - mu * mu;
        mean[c] = mu;
        invstd[c] = rsqrtf(var + 1e-5f);
    }
}

// conv_out: 64 -> 3, norm input (no relu), sigmoid epilogue. One pixel per thread.
__global__ __launch_bounds__(256)
void conv_out_k(const float* __restrict__ in, const float* __restrict__ w,
                const float* __restrict__ bias,
                const float* __restrict__ mean, const float* __restrict__ invstd,
                float* __restrict__ out)
{
    __shared__ float ws[3 * 64 * 9];
    __shared__ float tile[18 * 18];
    int bx = blockIdx.x;
    int x0 = (bx & 15) << 4, y0 = (bx >> 4) << 4;
    int tid = threadIdx.x;
    int px = tid & 15, py = tid >> 4;

    for (int e = tid; e < 3 * 64 * 9; e += 256) ws[e] = w[e];

    float a0 = 0.f, a1 = 0.f, a2 = 0.f;
    for (int cin = 0; cin < 64; cin++) {
        float mn = mean[cin], is = invstd[cin];
        for (int e = tid; e < 324; e += 256) {
            int iy = y0 + (e / 18) - 1, ix = x0 + (e % 18) - 1;
            float v = 0.f;
            if (iy >= 0 && iy < 256 && ix >= 0 && ix < 256)
                v = (in[cin * UVE + iy * 256 + ix] - mn) * is;
            tile[e] = v;
        }
        __syncthreads();
        float pr[9];
#pragma unroll
        for (int ky = 0; ky < 3; ky++)
#pragma unroll
            for (int kx = 0; kx < 3; kx++)
                pr[ky * 3 + kx] = tile[(py + ky) * 18 + px + kx];
#pragma unroll
        for (int k = 0; k < 9; k++) {
            a0 += pr[k] * ws[(0 * 64 + cin) * 9 + k];
            a1 += pr[k] * ws[(1 * 64 + cin) * 9 + k];
            a2 += pr[k] * ws[(2 * 64 + cin) * 9 + k];
        }
        __syncthreads();
    }
    int o = (y0 + py) * 256 + (x0 + px);
    a0 += bias[0]; a1 += bias[1]; a2 += bias[2];
    out[0 * UVE + o] = 1.f / (1.f + expf(-a0));
    out[1 * UVE + o] = 1.f / (1.f + expf(-a1));
    out[2 * UVE + o] = 1.f / (1.f + expf(-a2));
}

// ---------------- launch ----------------
extern "C" void kernel_launch(void* const* d_in, const int* in_sizes, int n_in,
                              void* d_out, int out_size)
{
    const float* latent_z  = (const float*)d_in[0];
    const float* latent_f  = (const float*)d_in[1];
    const float* cano_xyz  = (const float*)d_in[2];
    const float* m1_w_in   = (const float*)d_in[3];
    const float* m1_b_in   = (const float*)d_in[4];
    const float* m1_w_hid  = (const float*)d_in[5];
    const float* m1_b_hid  = (const float*)d_in[6];
    const float* m1_w_out  = (const float*)d_in[7];
    const float* m1_b_out  = (const float*)d_in[8];
    const float* m2_w_in   = (const float*)d_in[9];
    const float* m2_b_in   = (const float*)d_in[10];
    const float* m2_w_hid  = (const float*)d_in[11];
    const float* m2_b_hid  = (const float*)d_in[12];
    const float* m2_w_out  = (const float*)d_in[13];
    const float* m2_b_out  = (const float*)d_in[14];
    const float* conv_in_w = (const float*)d_in[15];
    const float* conv_in_b = (const float*)d_in[16];
    const float* conv_hid_w= (const float*)d_in[17];
    const float* conv_hid_b= (const float*)d_in[18];
    const float* conv_out_w= (const float*)d_in[19];
    const float* conv_out_b= (const float*)d_in[20];
    const int*   gs_part   = (const int*)d_in[21];
    const int*   uv_idx    = (const int*)d_in[22];
    float* outp = (float*)d_out;

    void *p_counts, *p_offsets, *p_cursor, *p_order, *p_uvmap, *p_bufA, *p_bufB, *p_mean, *p_invstd;
    cudaGetSymbolAddress(&p_counts, g_counts);
    cudaGetSymbolAddress(&p_offsets, g_offsets);
    cudaGetSymbolAddress(&p_cursor, g_cursor);
    cudaGetSymbolAddress(&p_order, g_order);
    cudaGetSymbolAddress(&p_uvmap, g_uvmap);
    cudaGetSymbolAddress(&p_bufA, g_bufA);
    cudaGetSymbolAddress(&p_bufB, g_bufB);
    cudaGetSymbolAddress(&p_mean, g_mean);
    cudaGetSymbolAddress(&p_invstd, g_invstd);

    cudaMemsetAsync(p_counts, 0, 8 * sizeof(int), 0);
    cudaMemsetAsync(p_uvmap, 0, 32 * UVE * sizeof(float), 0);

    int gb = (GN + 255) / 256;
    count_k<<<gb, 256>>>(gs_part, (int*)p_counts);
    scan_k<<<1, 32>>>((const int*)p_counts, (int*)p_offsets, (int*)p_cursor);
    scatter_k<<<gb, 256>>>(gs_part, (int*)p_cursor, (int*)p_order);

    static bool attr_set = false;
    if (!attr_set) {
        cudaFuncSetAttribute(mlp_k, cudaFuncAttributeMaxDynamicSharedMemorySize, 197632);
        attr_set = true;
    }
    mlp_k<<<PN * NTILES, 256, 197632>>>(
        latent_z, latent_f, cano_xyz,
        m1_w_in, m1_b_in, m1_w_hid, m1_b_hid, m1_w_out, m1_b_out,
        m2_w_in, m2_b_in, m2_w_hid, m2_b_hid, m2_w_out, m2_b_out,
        uv_idx, (const int*)p_order, (const int*)p_offsets, (float*)p_uvmap);

    float* bufA = (float*)p_bufA;
    float* bufB = (float*)p_bufB;
    float* mean = (float*)p_mean;
    float* invstd = (float*)p_invstd;

    // conv_in: uvmap(32) -> bufA(64), no relu, no norm
    conv64_k<32, false, false><<<256, 256>>>((const float*)p_uvmap, conv_in_w, conv_in_b, 0, 0, bufA);
    // hidden 0: relu(bufA) -> conv -> bufB; stats(bufB)
    conv64_k<64, true, false><<<256, 256>>>(bufA, conv_hid_w + 0 * 36864, conv_hid_b + 0, 0, 0, bufB);
    stats_k<<<64, 256>>>(bufB, mean, invstd);
    // hidden 1: relu(norm(bufB)) -> conv -> bufA; stats(bufA)
    conv64_k<64, true, true><<<256, 256>>>(bufB, conv_hid_w + 1 * 36864, conv_hid_b + 64, mean, invstd, bufA);
    stats_k<<<64, 256>>>(bufA, mean, invstd);
    // hidden 2: relu(norm(bufA)) -> conv -> bufB; stats(bufB)
    conv64_k<64, true, true><<<256, 256>>>(bufA, conv_hid_w + 2 * 36864, conv_hid_b + 128, mean, invstd, bufB);
    stats_k<<<64, 256>>>(bufB, mean, invstd);
    // conv_out: norm(bufB) -> conv(3) -> sigmoid -> out
    conv_out_k<<<256, 256>>>(bufB, conv_out_w, conv_out_b, mean, invstd, outp);
}

// round 3
// speedup vs baseline: 1.3698x; 1.3534x over previous
#include <cuda_runtime.h>
#include <math.h>

typedef unsigned long long ull;

#define GN 40000
#define PN 5
#define UVE 65536
#define TM 64
#define NT 625   // ceil(GN/TM)

__device__ __forceinline__ ull fma2(ull a, ull b, ull c) {
    ull d; asm("fma.rn.f32x2 %0, %1, %2, %3;" : "=l"(d) : "l"(a), "l"(b), "l"(c)); return d;
}
__device__ __forceinline__ ull pack2(float lo, float hi) {
    ull d; asm("mov.b64 %0, {%1, %2};" : "=l"(d) : "f"(lo), "f"(hi)); return d;
}
__device__ __forceinline__ void unpack2(ull v, float& lo, float& hi) {
    asm("mov.b64 {%0, %1}, %2;" : "=f"(lo), "=f"(hi) : "l"(v));
}

// ---------- scratch ----------
__device__ int    g_counts[8];
__device__ int    g_offsets[8];
__device__ int    g_cursor[8];
__device__ int    g_order[GN];
__device__ float  g_uvmap[32 * UVE];
__device__ float  g_bufA[64 * UVE];
__device__ float  g_bufB[64 * UVE];
__device__ float  g_mean[64];
__device__ float  g_invstd[64];
__device__ float2 g_wt[129024];   // dup weights: in[cin32][co64][9] @0 ; hid[l][cin64][co64][9] @18432

// ---------- bucketing ----------
__global__ void count_k(const int* __restrict__ part, int* counts) {
    int g = blockIdx.x * blockDim.x + threadIdx.x;
    if (g < GN) atomicAdd(&counts[part[g]], 1);
}
__global__ void scan_k(const int* __restrict__ counts, int* offsets, int* cursor) {
    if (threadIdx.x == 0) {
        int s = 0;
        for (int p = 0; p < PN; p++) { offsets[p] = s; cursor[p] = s; s += counts[p]; }
        offsets[PN] = s;
    }
}
__global__ void scatter_k(const int* __restrict__ part, int* cursor, int* __restrict__ order) {
    int g = blockIdx.x * blockDim.x + threadIdx.x;
    if (g < GN) { int pos = atomicAdd(&cursor[part[g]], 1); order[pos] = g; }
}

// ---------- conv weight transpose+duplicate ----------
__global__ void wprep_k(const float* __restrict__ win, const float* __restrict__ whid,
                        float2* __restrict__ wt) {
    int i = blockIdx.x * 256 + threadIdx.x;
    if (i < 18432) {              // [cin32][co64][9] <- OIHW [64][32][9]
        int k = i % 9; int t = i / 9; int co = t % 64, cin = t / 64;
        float v = win[(co * 32 + cin) * 9 + k];
        wt[i] = make_float2(v, v);
    }
    if (i < 110592) {             // [l][cin64][co64][9] <- [l][64][64][9]
        int k = i % 9; int t = i / 9; int co = t % 64;
        int t2 = t / 64; int cin = t2 % 64, l = t2 / 64;
        float v = whid[((l * 64 + co) * 64 + cin) * 9 + k];
        wt[18432 + i] = make_float2(v, v);
    }
}

// ---------- fused MLP (f32x2, double-buffered weights) ----------
// A k-major [K][64]. 8 warps; warp w owns cols [16w,16w+16); lane: r0=(lane&15)*4, c0=16w+8*(lane>>4).
template<int MODE>  // 0: lrelu->Out  1: masked cols->Out  2: masked, scatter uvmap
__device__ __forceinline__ void layer2(
    const float* A, int K, int NC,
    const float* __restrict__ W, int N, const float* __restrict__ bias,
    float* Out, float* Bs, int tid,
    const int* s_uv, float* uvmap, int m)
{
    const int w = tid >> 5, lane = tid & 31;
    const int r0 = (lane & 15) << 2;
    const int c0 = (w << 4) + ((lane >> 4) << 3);
    const bool active = (w << 4) < N;

    ull acc[4][4];
#pragma unroll
    for (int r = 0; r < 4; r++)
#pragma unroll
        for (int cp = 0; cp < 4; cp++) acc[r][cp] = 0ull;

    float wpf[8];
#pragma unroll
    for (int t = 0; t < 8; t++) {
        int e = tid + (t << 8); int kk = e >> 7, j = e & 127;
        wpf[t] = (kk < K && j < N) ? W[kk * N + j] : 0.f;
    }

    for (int ch = 0; ch < NC; ch++) {
        float* B = Bs + ((ch & 1) << 11);
#pragma unroll
        for (int t = 0; t < 8; t++) B[tid + (t << 8)] = wpf[t];
        __syncthreads();
        if (ch + 1 < NC) {
            int kb = (ch + 1) << 4;
#pragma unroll
            for (int t = 0; t < 8; t++) {
                int e = tid + (t << 8); int kk = kb + (e >> 7), j = e & 127;
                wpf[t] = (kk < K && j < N) ? W[kk * N + j] : 0.f;
            }
        }
        if (active) {
            const float* Ak = A + (ch << 4) * TM + r0;
            const float* Bk = B + c0;
#pragma unroll
            for (int kk = 0; kk < 16; kk++) {
                float4 a4 = *(const float4*)(Ak + (kk << 6));
                ulonglong2 b01 = *(const ulonglong2*)(Bk + (kk << 7));
                ulonglong2 b23 = *(const ulonglong2*)(Bk + (kk << 7) + 4);
                ull ar[4] = { pack2(a4.x, a4.x), pack2(a4.y, a4.y),
                              pack2(a4.z, a4.z), pack2(a4.w, a4.w) };
                ull bp[4] = { b01.x, b01.y, b23.x, b23.y };
#pragma unroll
                for (int r = 0; r < 4; r++)
#pragma unroll
                    for (int cp = 0; cp < 4; cp++)
                        acc[r][cp] = fma2(ar[r], bp[cp], acc[r][cp]);
            }
        }
    }

    if (active) {
#pragma unroll
        for (int cp = 0; cp < 4; cp++) {
            int c = c0 + (cp << 1);
            float lo, hi;
            if (MODE == 0) {
                float blo = bias[c], bhi = bias[c + 1];
#pragma unroll
                for (int r = 0; r < 4; r++) {
                    unpack2(acc[r][cp], lo, hi);
                    lo += blo; hi += bhi;
                    Out[c * TM + r0 + r]       = lo > 0.f ? lo : 0.01f * lo;
                    Out[(c + 1) * TM + r0 + r] = hi > 0.f ? hi : 0.01f * hi;
                }
            } else if (MODE == 1) {
#pragma unroll
                for (int r = 0; r < 4; r++) {
                    unpack2(acc[r][cp], lo, hi);
                    if (c < N)     Out[c * TM + r0 + r]       = lo + bias[c];
                    if (c + 1 < N) Out[(c + 1) * TM + r0 + r] = hi + bias[c + 1];
                }
            } else {
                float blo = bias[c], bhi = bias[c + 1];
#pragma unroll
                for (int r = 0; r < 4; r++) {
                    if (r0 + r < m) {
                        int uv = s_uv[r0 + r];
                        unpack2(acc[r][cp], lo, hi);
                        uvmap[c * UVE + uv]       = lo + blo;
                        uvmap[(c + 1) * UVE + uv] = hi + bhi;
                    }
                }
            }
        }
    }
    __syncthreads();
}

__global__ __launch_bounds__(256, 2)
void mlp_k(const float* __restrict__ latent_z, const float* __restrict__ latent_f,
           const float* __restrict__ cano_xyz,
           const float* __restrict__ m1_w_in, const float* __restrict__ m1_b_in,
           const float* __restrict__ m1_w_hid, const float* __restrict__ m1_b_hid,
           const float* __restrict__ m1_w_out, const float* __restrict__ m1_b_out,
           const float* __restrict__ m2_w_in, const float* __restrict__ m2_b_in,
           const float* __restrict__ m2_w_hid, const float* __restrict__ m2_b_hid,
           const float* __restrict__ m2_w_out, const float* __restrict__ m2_b_out,
           const int* __restrict__ uv_idx,
           const int* __restrict__ order, const int* __restrict__ offsets,
           float* __restrict__ uvmap)
{
    extern __shared__ float sm[];
    float* Xs = sm;                        // [112][64]
    float* Hp = Xs + 112 * TM;             // [128][64]
    float* Hq = Hp + 128 * TM;             // [128][64]
    float* Bs = Hq + 128 * TM;             // [2][2048]
    int*   s_idx = (int*)(Bs + 4096);      // [64]
    int*   s_uv  = s_idx + TM;             // [64]

    int p = blockIdx.x / NT;
    int t = blockIdx.x % NT;
    int beg = offsets[p], end = offsets[p + 1];
    int start = beg + t * TM;
    if (start >= end) return;
    int m = min(TM, end - start);
    int tid = threadIdx.x;

    if (tid < TM) {
        int rr = tid < m ? tid : (m - 1);
        int gid = order[start + rr];
        s_idx[tid] = gid;
        s_uv[tid] = uv_idx[gid];
    }
    __syncthreads();

    for (int e = tid; e < 112 * TM; e += 256) {
        int d = e >> 6, r = e & 63;
        float v = 0.f;
        if (d < 64)       v = latent_f[p * 64 + d];
        else if (d < 96)  v = latent_z[s_idx[r] * 32 + (d - 64)];
        else if (d < 99)  v = cano_xyz[s_idx[r] * 3 + (d - 96)];
        Xs[e] = v;
    }

    layer2<0>(Xs, 96, 6,  m1_w_in  + p * 96 * 128, 128, m1_b_in  + p * 128, Hp, Bs, tid, 0, 0, m);
    layer2<0>(Hp, 128, 8, m1_w_hid + (p * 2 + 0) * 16384, 128, m1_b_hid + (p * 2 + 0) * 128, Hq, Bs, tid, 0, 0, m);
    layer2<0>(Hq, 128, 8, m1_w_hid + (p * 2 + 1) * 16384, 128, m1_b_hid + (p * 2 + 1) * 128, Hp, Bs, tid, 0, 0, m);
    layer2<1>(Hp, 128, 8, m1_w_out + p * 128 * 11, 11, m1_b_out + p * 11, Xs + 99 * TM, Bs, tid, 0, 0, m);
    layer2<0>(Xs, 110, 7, m2_w_in  + p * 110 * 128, 128, m2_b_in  + p * 128, Hp, Bs, tid, 0, 0, m);
    layer2<0>(Hp, 128, 8, m2_w_hid + (p * 2 + 0) * 16384, 128, m2_b_hid + (p * 2 + 0) * 128, Hq, Bs, tid, 0, 0, m);
    layer2<0>(Hq, 128, 8, m2_w_hid + (p * 2 + 1) * 16384, 128, m2_b_hid + (p * 2 + 1) * 128, Hp, Bs, tid, 0, 0, m);
    layer2<2>(Hp, 128, 8, m2_w_out + p * 128 * 32, 32, m2_b_out + p * 32, (float*)0, Bs, tid, s_uv, uvmap, m);
}

// ---------- CNN ----------
template<bool NORM, bool RELU>
__device__ __forceinline__ float conv_val(const float* __restrict__ in, int cin,
                                          int x0, int y0, int e, float mn, float is) {
    int row = e / 18, col = e - row * 18;
    int iy = y0 + row - 1, ix = x0 + col - 1;
    float v = 0.f;
    if (iy >= 0 && iy < 256 && ix >= 0 && ix < 256) {
        v = in[cin * UVE + iy * 256 + ix];
        if (NORM) v = (v - mn) * is;
        if (RELU) v = fmaxf(v, 0.f);
    }
    return v;
}

// 16x16 px x 64 co per block. Thread: 2x2 px (pg=tid&63) x 16 co (cg=tid>>6). f32x2 over px pairs.
// tB is tA shifted by +1 so odd-offset pairs are aligned LDS.64.
template<int CIN, bool RELU, bool NORM>
__global__ __launch_bounds__(256, 2)
void conv64_k(const float* __restrict__ in, const float2* __restrict__ wt,
              const float* __restrict__ bias,
              const float* __restrict__ mean, const float* __restrict__ invstd,
              float* __restrict__ out)
{
    __shared__ __align__(16) float tA[2][324];
    __shared__ __align__(16) float tB[2][328];
    __shared__ __align__(16) float2 ws[2][576];

    const int bx = blockIdx.x;
    const int x0 = (bx & 15) << 4, y0 = (bx >> 4) << 4;
    const int tid = threadIdx.x;
    const int pg = tid & 63, cg = tid >> 6;
    const int lx = (pg & 7) << 1, ly = (pg >> 3) << 1;

    ull acc[16][2];
#pragma unroll
    for (int co = 0; co < 16; co++) { acc[co][0] = 0ull; acc[co][1] = 0ull; }

    float tv0, tv1 = 0.f;
    float2 wv0, wv1, wv2 = make_float2(0.f, 0.f);
    {
        float mn = NORM ? mean[0] : 0.f, is = NORM ? invstd[0] : 1.f;
        tv0 = conv_val<NORM, RELU>(in, 0, x0, y0, tid, mn, is);
        if (tid < 68) tv1 = conv_val<NORM, RELU>(in, 0, x0, y0, tid + 256, mn, is);
        wv0 = wt[tid]; wv1 = wt[tid + 256];
        if (tid < 64) wv2 = wt[tid + 512];
    }

    for (int cin = 0; cin < CIN; cin++) {
        const int b = cin & 1;
        tA[b][tid] = tv0; tB[b][tid + 1] = tv0;
        if (tid < 68) { tA[b][tid + 256] = tv1; tB[b][tid + 257] = tv1; }
        ws[b][tid] = wv0; ws[b][tid + 256] = wv1;
        if (tid < 64) ws[b][tid + 512] = wv2;
        __syncthreads();
        if (cin + 1 < CIN) {
            int c2 = cin + 1;
            float mn = NORM ? mean[c2] : 0.f, is = NORM ? invstd[c2] : 1.f;
            tv0 = conv_val<NORM, RELU>(in, c2, x0, y0, tid, mn, is);
            if (tid < 68) tv1 = conv_val<NORM, RELU>(in, c2, x0, y0, tid + 256, mn, is);
            const float2* wp = wt + c2 * 576;
            wv0 = wp[tid]; wv1 = wp[tid + 256];
            if (tid < 64) wv2 = wp[tid + 512];
        }
        // pixel pairs: rows ly..ly+3, pairs P(base+kx) for kx=0..2
        ull pp[4][3];
#pragma unroll
        for (int r = 0; r < 4; r++) {
            int base = (ly + r) * 18 + lx;
            pp[r][0] = *(const ull*)&tA[b][base];
            pp[r][1] = *(const ull*)&tB[b][base + 2];
            pp[r][2] = *(const ull*)&tA[b][base + 2];
        }
        const float2* wpp = ws[b] + (cg << 4) * 9;
#pragma unroll
        for (int co = 0; co < 16; co++)
#pragma unroll
            for (int ky = 0; ky < 3; ky++)
#pragma unroll
                for (int kx = 0; kx < 3; kx++) {
                    ull w2 = *(const ull*)&wpp[co * 9 + ky * 3 + kx];
                    acc[co][0] = fma2(pp[ky][kx],     w2, acc[co][0]);
                    acc[co][1] = fma2(pp[ky + 1][kx], w2, acc[co][1]);
                }
        __syncthreads();
    }

#pragma unroll
    for (int co = 0; co < 16; co++) {
        int c = (cg << 4) + co;
        float bb = bias[c];
        float lo, hi;
        float* op = out + c * UVE + (y0 + ly) * 256 + (x0 + lx);
        unpack2(acc[co][0], lo, hi); *(float2*)op         = make_float2(lo + bb, hi + bb);
        unpack2(acc[co][1], lo, hi); *(float2*)(op + 256) = make_float2(lo + bb, hi + bb);
    }
}

__global__ void stats_k(const float* __restrict__ buf, float* mean, float* invstd) {
    __shared__ float s1[256], s2[256];
    int c = blockIdx.x, tid = threadIdx.x;
    float a = 0.f, b = 0.f;
    for (int i = tid; i < UVE; i += 256) {
        float v = buf[c * UVE + i];
        a += v; b += v * v;
    }
    s1[tid] = a; s2[tid] = b;
    __syncthreads();
    for (int s = 128; s > 0; s >>= 1) {
        if (tid < s) { s1[tid] += s1[tid + s]; s2[tid] += s2[tid + s]; }
        __syncthreads();
    }
    if (tid == 0) {
        float mu = s1[0] * (1.f / UVE);
        float var = s2[0] * (1.f / UVE) - mu * mu;
        mean[c] = mu;
        invstd[c] = rsqrtf(var + 1e-5f);
    }
}

__global__ __launch_bounds__(256)
void conv_out_k(const float* __restrict__ in, const float* __restrict__ w,
                const float* __restrict__ bias,
                const float* __restrict__ mean, const float* __restrict__ invstd,
                float* __restrict__ out)
{
    __shared__ float ws[3 * 64 * 9];
    __shared__ float tile[18 * 18];
    int bx = blockIdx.x;
    int x0 = (bx & 15) << 4, y0 = (bx >> 4) << 4;
    int tid = threadIdx.x;
    int px = tid & 15, py = tid >> 4;

    for (int e = tid; e < 3 * 64 * 9; e += 256) ws[e] = w[e];

    float a0 = 0.f, a1 = 0.f, a2 = 0.f;
    for (int cin = 0; cin < 64; cin++) {
        float mn = mean[cin], is = invstd[cin];
        for (int e = tid; e < 324; e += 256)
            tile[e] = conv_val<true, false>(in, cin, x0, y0, e, mn, is);
        __syncthreads();
        float pr[9];
#pragma unroll
        for (int ky = 0; ky < 3; ky++)
#pragma unroll
            for (int kx = 0; kx < 3; kx++)
                pr[ky * 3 + kx] = tile[(py + ky) * 18 + px + kx];
#pragma unroll
        for (int k = 0; k < 9; k++) {
            a0 += pr[k] * ws[(0 * 64 + cin) * 9 + k];
            a1 += pr[k] * ws[(1 * 64 + cin) * 9 + k];
            a2 += pr[k] * ws[(2 * 64 + cin) * 9 + k];
        }
        __syncthreads();
    }
    int o = (y0 + py) * 256 + (x0 + px);
    a0 += bias[0]; a1 += bias[1]; a2 += bias[2];
    out[0 * UVE + o] = 1.f / (1.f + expf(-a0));
    out[1 * UVE + o] = 1.f / (1.f + expf(-a1));
    out[2 * UVE + o] = 1.f / (1.f + expf(-a2));
}

// ---------- launch ----------
extern "C" void kernel_launch(void* const* d_in, const int* in_sizes, int n_in,
                              void* d_out, int out_size)
{
    const float* latent_z  = (const float*)d_in[0];
    const float* latent_f  = (const float*)d_in[1];
    const float* cano_xyz  = (const float*)d_in[2];
    const float* m1_w_in   = (const float*)d_in[3];
    const float* m1_b_in   = (const float*)d_in[4];
    const float* m1_w_hid  = (const float*)d_in[5];
    const float* m1_b_hid  = (const float*)d_in[6];
    const float* m1_w_out  = (const float*)d_in[7];
    const float* m1_b_out  = (const float*)d_in[8];
    const float* m2_w_in   = (const float*)d_in[9];
    const float* m2_b_in   = (const float*)d_in[10];
    const float* m2_w_hid  = (const float*)d_in[11];
    const float* m2_b_hid  = (const float*)d_in[12];
    const float* m2_w_out  = (const float*)d_in[13];
    const float* m2_b_out  = (const float*)d_in[14];
    const float* conv_in_w = (const float*)d_in[15];
    const float* conv_in_b = (const float*)d_in[16];
    const float* conv_hid_w= (const float*)d_in[17];
    const float* conv_hid_b= (const float*)d_in[18];
    const float* conv_out_w= (const float*)d_in[19];
    const float* conv_out_b= (const float*)d_in[20];
    const int*   gs_part   = (const int*)d_in[21];
    const int*   uv_idx    = (const int*)d_in[22];
    float* outp = (float*)d_out;

    void *p_counts, *p_offsets, *p_cursor, *p_order, *p_uvmap, *p_bufA, *p_bufB, *p_mean, *p_invstd, *p_wt;
    cudaGetSymbolAddress(&p_counts, g_counts);
    cudaGetSymbolAddress(&p_offsets, g_offsets);
    cudaGetSymbolAddress(&p_cursor, g_cursor);
    cudaGetSymbolAddress(&p_order, g_order);
    cudaGetSymbolAddress(&p_uvmap, g_uvmap);
    cudaGetSymbolAddress(&p_bufA, g_bufA);
    cudaGetSymbolAddress(&p_bufB, g_bufB);
    cudaGetSymbolAddress(&p_mean, g_mean);
    cudaGetSymbolAddress(&p_invstd, g_invstd);
    cudaGetSymbolAddress(&p_wt, g_wt);

    cudaMemsetAsync(p_counts, 0, 8 * sizeof(int), 0);
    cudaMemsetAsync(p_uvmap, 0, 32 * UVE * sizeof(float), 0);

    wprep_k<<<432, 256>>>(conv_in_w, conv_hid_w, (float2*)p_wt);

    int gb = (GN + 255) / 256;
    count_k<<<gb, 256>>>(gs_part, (int*)p_counts);
    scan_k<<<1, 32>>>((const int*)p_counts, (int*)p_offsets, (int*)p_cursor);
    scatter_k<<<gb, 256>>>(gs_part, (int*)p_cursor, (int*)p_order);

    static bool attr_set = false;
    if (!attr_set) {
        cudaFuncSetAttribute(mlp_k, cudaFuncAttributeMaxDynamicSharedMemorySize, 111104);
        attr_set = true;
    }
    mlp_k<<<PN * NT, 256, 111104>>>(
        latent_z, latent_f, cano_xyz,
        m1_w_in, m1_b_in, m1_w_hid, m1_b_hid, m1_w_out, m1_b_out,
        m2_w_in, m2_b_in, m2_w_hid, m2_b_hid, m2_w_out, m2_b_out,
        uv_idx, (const int*)p_order, (const int*)p_offsets, (float*)p_uvmap);

    float* bufA = (float*)p_bufA;
    float* bufB = (float*)p_bufB;
    float* mean = (float*)p_mean;
    float* invstd = (float*)p_invstd;
    const float2* wt = (const float2*)p_wt;

    conv64_k<32, false, false><<<256, 256>>>((const float*)p_uvmap, wt, conv_in_b, 0, 0, bufA);
    conv64_k<64, true, false><<<256, 256>>>(bufA, wt + 18432, conv_hid_b, 0, 0, bufB);
    stats_k<<<64, 256>>>(bufB, mean, invstd);
    conv64_k<64, true, true><<<256, 256>>>(bufB, wt + 18432 + 36864, conv_hid_b + 64, mean, invstd, bufA);
    stats_k<<<64, 256>>>(bufA, mean, invstd);
    conv64_k<64, true, true><<<256, 256>>>(bufA, wt + 18432 + 2 * 36864, conv_hid_b + 128, mean, invstd, bufB);
    stats_k<<<64, 256>>>(bufB, mean, invstd);
    conv_out_k<<<256, 256>>>(bufB, conv_out_w, conv_out_b, mean, invstd, outp);
}